// round 5
// baseline (speedup 1.0000x reference)
#include <cuda_runtime.h>
#include <stdint.h>

#define GH 52
#define GW 52
#define NB 5
#define NBOX 13520                 // 52*52*5
#define ROWBITS 288                // padded bits per grid row (260 used)
#define PWORDS 468                 // 52 rows * 9 words
#define PPOS   (PWORDS*32)         // 14976 padded bit positions
#define PADW   12                  // zero padding words each side of kept
#define NMS_T  1024
#define NWARP  32
#define SLOTS  15                  // contiguous words per warp (32*15=480>=468)
#define IOU_T  0.4f

// Per-position predecessor masks (padded layout). x=row dy=-1, y=dy=0,
// z=dy=+1, 15 bits each (bit (dx+1)*5+bb). Zero-initialized; only valid
// positions are written.
__device__ ushort4 g_pm[PPOS];

// ---------------------------------------------------------------------------
// Kernel 1: decode + per-row predecessor masks. One thread per (box, dyRow).
// Identical fp32 op sequence as the reference decode -> exact.
// Branchless inner: whole 25-float neighbor cell loaded up front (parallel
// loads), IoU computed unconditionally, bit accumulated by predicate.
// ---------------------------------------------------------------------------
__global__ void decode_kernel(const float* __restrict__ x, float* __restrict__ out)
{
    int id = blockIdx.x * blockDim.x + threadIdx.x;
    if (id >= 3 * NBOX) return;
    int dyI = id / NBOX;            // 0,1,2 -> dy = dyI-1
    int j   = id - dyI * NBOX;

    int cell = j / NB;
    int b    = j - cell * NB;
    int gy   = cell / GW;
    int gx   = cell - gy * GW;

    const float sx = 416.0f / GW;   // 8
    const float sy = 416.0f / GH;   // 8

    const float* p = x + j * 5;
    float c0 = p[0], c1 = p[1], c2 = p[2], c3 = p[3], sj = p[4];

    float cx = (c0 + (float)gx) * sx;
    float w  = c2 * sx;
    float cy = (c1 + (float)gy) * sy;
    float h  = c3 * sy;
    cy = 416.0f - cy;
    float jx1 = cx - w * 0.5f, jy1 = cy - h * 0.5f;
    float jx2 = cx + w * 0.5f, jy2 = cy + h * 0.5f;

    if (dyI == 1) {
        float* o = out + j * 5;
        o[0] = jx1; o[1] = jy1; o[2] = jx2; o[3] = jy2;
        // o[4] written by nms_kernel.
    }

    float aj = fmaxf(jx2 - jx1, 0.0f) * fmaxf(jy2 - jy1, 0.0f);

    unsigned mask = 0;
    int ny = gy + dyI - 1;
    if ((unsigned)ny < GH) {
        #pragma unroll
        for (int dxi = 0; dxi < 3; dxi++) {
            int nx = gx + dxi - 1;
            if ((unsigned)nx >= GW) continue;
            int ncell = ny * GW + nx;
            const float* cp = x + ncell * 25;
            float q[25];
            #pragma unroll
            for (int k = 0; k < 25; k++) q[k] = cp[k];

            #pragma unroll
            for (int bb = 0; bb < NB; bb++) {
                int i = ncell * NB + bb;
                float si = q[bb * 5 + 4];
                bool higher = (si > sj) || (si == sj && i < j);
                float d0 = q[bb * 5 + 0], d1 = q[bb * 5 + 1];
                float d2 = q[bb * 5 + 2], d3 = q[bb * 5 + 3];
                float icx = (d0 + (float)nx) * sx;
                float iw_ = d2 * sx;
                float icy = (d1 + (float)ny) * sy;
                float ih_ = d3 * sy;
                icy = 416.0f - icy;
                float ix1 = icx - iw_ * 0.5f, iy1 = icy - ih_ * 0.5f;
                float ix2 = icx + iw_ * 0.5f, iy2 = icy + ih_ * 0.5f;

                float iw = fmaxf(fminf(ix2, jx2) - fmaxf(ix1, jx1), 0.0f);
                float ih = fmaxf(fminf(iy2, jy2) - fmaxf(iy1, jy1), 0.0f);
                float inter = iw * ih;
                float ai  = fmaxf(ix2 - ix1, 0.0f) * fmaxf(iy2 - iy1, 0.0f);
                float uni = ai + aj - inter;
                float iou = (uni > 0.0f) ? inter / fmaxf(uni, 1e-12f) : 0.0f;
                bool on = (iou > IOU_T) && higher && (i != j);
                mask |= (on ? 1u : 0u) << (dxi * 5 + bb);
            }
        }
    }
    // padded bit position of box j
    int pos = gy * ROWBITS + gx * 5 + b;
    ((unsigned short*)&g_pm[pos])[dyI] = (unsigned short)mask;
}

// ---------------------------------------------------------------------------
// Kernel 2: single-CTA fixpoint NMS, row-padded layout, in-place
// Gauss-Seidel with word-granular dirty-window frontier.
// kept[p] = valid(p) && no kept higher-priority overlapper. Unique fixpoint
// == exact greedy NMS; a zero-change iteration certifies it (frontier
// invariant: a skipped word's inputs are unchanged since its last eval).
// ---------------------------------------------------------------------------
__device__ __forceinline__ uint32_t gather15(const uint32_t* L, int bit)
{
    int wi = bit >> 5;
    return __funnelshift_r(L[wi], L[wi + 1], bit) & 0x7FFFu;
}

__global__ void __launch_bounds__(NMS_T, 1)
nms_kernel(const float* __restrict__ x, float* __restrict__ out)
{
    __shared__ uint32_t L[PADW + PWORDS + PADW];   // 492 words
    __shared__ uint32_t dm[3][18];                 // dirty maps, bit (w+22)

    int t    = threadIdx.x;
    int lane = t & 31;
    int wid  = t >> 5;

    // Init kept bitmap: valid bits 1, padding 0.
    for (int i = t; i < PADW + PWORDS + PADW; i += NMS_T) {
        int w = i - PADW;
        uint32_t v = 0;
        if (w >= 0 && w < PWORDS)
            v = ((w % 9) == 8) ? 0xFu : 0xFFFFFFFFu;   // word 8 of a row: 4 valid bits
        L[i] = v;
    }
    if (t < 18) { dm[0][t] = 0xFFFFFFFFu; dm[1][t] = 0; dm[2][t] = 0; }

    // Per-slot precompute (contiguous words per warp).
    int wBase = wid * SLOTS;
    int lbs[SLOTS];
    uint32_t vm15 = 0;           // bit s: word is a row-tail word (4 valid bits)
    #pragma unroll
    for (int s = 0; s < SLOTS; s++) {
        int w = wBase + s;
        int p = w * 32 + lane;
        int row = p / ROWBITS;
        int rem = p - row * ROWBITS;
        int b   = rem % 5;
        lbs[s] = PADW * 32 + p - b - 5;
        if ((w % 9) == 8) vm15 |= 1u << s;
    }
    __syncthreads();

    int a = 0, bw = 1, c = 2;    // read / write / clear dirty slots
    for (int it = 0; it < 4096; it++) {
        if (t < 18) dm[c][t] = 0;

        uint32_t chm = 0;        // lane0: per-slot change bits
        #pragma unroll
        for (int s = 0; s < SLOTS; s++) {
            int w = wBase + s;
            if (w >= PWORDS) break;
            // dirty window [w-10, w+10] -> bits (w+12 .. w+32) of map
            int bi = w + 12;
            uint64_t win = (uint64_t)dm[a][bi >> 5] |
                           ((uint64_t)dm[a][(bi >> 5) + 1] << 32);
            if (((win >> (bi & 31)) & 0x1FFFFFu) == 0) continue;

            int p = w * 32 + lane;
            ushort4 pm = __ldg(&g_pm[p]);
            int lb = lbs[s];
            uint32_t gu = gather15(L, lb - ROWBITS);
            uint32_t gm = gather15(L, lb);
            uint32_t gd = gather15(L, lb + ROWBITS);
            uint32_t sup = (gu & pm.x) | (gm & pm.y) | (gd & pm.z);
            uint32_t nw = __ballot_sync(0xFFFFFFFFu, sup == 0u);
            nw &= ((vm15 >> s) & 1u) ? 0xFu : 0xFFFFFFFFu;
            if (lane == 0) {
                if (L[PADW + w] != nw) { L[PADW + w] = nw; chm |= 1u << s; }
            }
        }

        int ch = 0;
        if (lane == 0 && chm) {
            ch = 1;
            int bb = wBase + 22;                     // dirty bit base
            uint64_t m = (uint64_t)chm << (bb & 31);
            atomicOr(&dm[bw][bb >> 5], (uint32_t)m);
            uint32_t hi = (uint32_t)(m >> 32);
            if (hi) atomicOr(&dm[bw][(bb >> 5) + 1], hi);
        }
        int any = __syncthreads_or(ch);
        if (!any) break;
        int tmp = a; a = bw; bw = c; c = tmp;
    }

    // Writeout: score if kept else 0.
    #pragma unroll
    for (int s = 0; s < SLOTS; s++) {
        int w = wBase + s;
        if (w >= PWORDS) break;
        int p = w * 32 + lane;
        int row = p / ROWBITS;
        int rem = p - row * ROWBITS;
        if (rem < 260) {
            int j = row * 260 + rem;
            bool keep = (L[PADW + w] >> lane) & 1u;
            out[j * 5 + 4] = keep ? __ldg(&x[j * 5 + 4]) : 0.0f;
        }
    }
}

// ---------------------------------------------------------------------------
extern "C" void kernel_launch(void* const* d_in, const int* in_sizes, int n_in,
                              void* d_out, int out_size)
{
    const float* x   = (const float*)d_in[0];
    float*       out = (float*)d_out;

    decode_kernel<<<(3 * NBOX + 255) / 256, 256>>>(x, out);
    nms_kernel<<<1, NMS_T>>>(x, out);
}

// round 6
// speedup vs baseline: 1.8528x; 1.8528x over previous
#include <cuda_runtime.h>
#include <cooperative_groups.h>
#include <stdint.h>

namespace cg = cooperative_groups;

#define GH 52
#define GW 52
#define NB 5
#define NBOX 13520                 // 52*52*5
#define ROWBITS 288                // padded bits per grid row (260 used)
#define RWORDS 9                   // words per grid row
#define PWORDS 468                 // 52 * 9
#define PPOS   (PWORDS*32)
#define IOU_T  0.4f

#define CTAS   4
#define ROWS_PER 13                // 52/4, row-aligned strips
#define OWNW   (ROWS_PER*RWORDS)   // 117 words per CTA
#define LBASE  10                  // 1 pad word + 9 halo words below
#define LSZ    (LBASE + OWNW + 10 + 1)   // +9 halo +1 pad/straddle = 138
#define NMS_T  1024
#define SLOTS  4                   // 32 warps * 4 = 128 >= 117

// Per-position predecessor masks (padded layout). x=row dy=-1, y=dy=0,
// z=dy=+1, 15 bits each (bit (dx+1)*5+bb). Padding positions stay zero.
__device__ ushort4 g_pm[PPOS];

// ---------------------------------------------------------------------------
// Kernel 1: decode + per-row predecessor masks (R5 version, proven fast+exact)
// ---------------------------------------------------------------------------
__global__ void decode_kernel(const float* __restrict__ x, float* __restrict__ out)
{
    int id = blockIdx.x * blockDim.x + threadIdx.x;
    if (id >= 3 * NBOX) return;
    int dyI = id / NBOX;            // 0,1,2 -> dy = dyI-1
    int j   = id - dyI * NBOX;

    int cell = j / NB;
    int b    = j - cell * NB;
    int gy   = cell / GW;
    int gx   = cell - gy * GW;

    const float sx = 416.0f / GW;   // 8
    const float sy = 416.0f / GH;   // 8

    const float* p = x + j * 5;
    float c0 = p[0], c1 = p[1], c2 = p[2], c3 = p[3], sj = p[4];

    float cx = (c0 + (float)gx) * sx;
    float w  = c2 * sx;
    float cy = (c1 + (float)gy) * sy;
    float h  = c3 * sy;
    cy = 416.0f - cy;
    float jx1 = cx - w * 0.5f, jy1 = cy - h * 0.5f;
    float jx2 = cx + w * 0.5f, jy2 = cy + h * 0.5f;

    if (dyI == 1) {
        float* o = out + j * 5;
        o[0] = jx1; o[1] = jy1; o[2] = jx2; o[3] = jy2;
        // o[4] written by nms_kernel.
    }

    float aj = fmaxf(jx2 - jx1, 0.0f) * fmaxf(jy2 - jy1, 0.0f);

    unsigned mask = 0;
    int ny = gy + dyI - 1;
    if ((unsigned)ny < GH) {
        #pragma unroll
        for (int dxi = 0; dxi < 3; dxi++) {
            int nx = gx + dxi - 1;
            if ((unsigned)nx >= GW) continue;
            int ncell = ny * GW + nx;
            const float* cp = x + ncell * 25;
            float q[25];
            #pragma unroll
            for (int k = 0; k < 25; k++) q[k] = cp[k];

            #pragma unroll
            for (int bb = 0; bb < NB; bb++) {
                int i = ncell * NB + bb;
                float si = q[bb * 5 + 4];
                bool higher = (si > sj) || (si == sj && i < j);
                float d0 = q[bb * 5 + 0], d1 = q[bb * 5 + 1];
                float d2 = q[bb * 5 + 2], d3 = q[bb * 5 + 3];
                float icx = (d0 + (float)nx) * sx;
                float iw_ = d2 * sx;
                float icy = (d1 + (float)ny) * sy;
                float ih_ = d3 * sy;
                icy = 416.0f - icy;
                float ix1 = icx - iw_ * 0.5f, iy1 = icy - ih_ * 0.5f;
                float ix2 = icx + iw_ * 0.5f, iy2 = icy + ih_ * 0.5f;

                float iw = fmaxf(fminf(ix2, jx2) - fmaxf(ix1, jx1), 0.0f);
                float ih = fmaxf(fminf(iy2, jy2) - fmaxf(iy1, jy1), 0.0f);
                float inter = iw * ih;
                float ai  = fmaxf(ix2 - ix1, 0.0f) * fmaxf(iy2 - iy1, 0.0f);
                float uni = ai + aj - inter;
                float iou = (uni > 0.0f) ? inter / fmaxf(uni, 1e-12f) : 0.0f;
                bool on = (iou > IOU_T) && higher && (i != j);
                mask |= (on ? 1u : 0u) << (dxi * 5 + bb);
            }
        }
    }
    int pos = gy * ROWBITS + gx * 5 + b;
    ((unsigned short*)&g_pm[pos])[dyI] = (unsigned short)mask;
}

// ---------------------------------------------------------------------------
// Kernel 2: row-aligned clustered hierarchical fixpoint NMS.
// 4 CTAs x 13 grid rows. Per outer sweep: DSMEM halo refresh (diff-tracked),
// inner Gauss-Seidel to local fixpoint (dirty-window frontier, block
// barriers), one cluster.sync, 4-flag convergence exchange. Terminates when
// no CTA changed anything in a sweep => certified exact greedy fixpoint.
// ---------------------------------------------------------------------------
__device__ __forceinline__ uint32_t gather15(const uint32_t* L, int bit)
{
    int wi = bit >> 5;
    return __funnelshift_r(L[wi], L[wi + 1], bit) & 0x7FFFu;
}

__global__ void __cluster_dims__(CTAS, 1, 1) __launch_bounds__(NMS_T, 1)
nms_kernel(const float* __restrict__ x, float* __restrict__ out)
{
    __shared__ uint32_t L[LSZ];         // 138 words
    __shared__ uint32_t dm[3][5];       // dirty maps, bit = local word index
    __shared__ int sCh[3];
    __shared__ int sAny;

    cg::cluster_group cl = cg::this_cluster();
    int r    = cl.block_rank();
    int t    = threadIdx.x;
    int lane = t & 31;
    int wid  = t >> 5;

    int ow0 = r * OWNW;                 // first own global word

    // Init kept bitmap: valid bits 1 (row-tail words keep 4 bits), pads 0.
    for (int i = t; i < LSZ; i += NMS_T) {
        int gw = ow0 + i - LBASE;
        uint32_t v = 0;
        if (gw >= 0 && gw < PWORDS)
            v = ((gw % 9) == 8) ? 0xFu : 0xFFFFFFFFu;
        L[i] = v;
    }
    if (t < 5) { dm[0][t] = 0xFFFFFFFFu; dm[1][t] = 0; dm[2][t] = 0; }
    if (t < 3) sCh[t] = 0;
    if (t == 0) sAny = 1;

    uint32_t* Lprev = (r > 0)        ? (uint32_t*)cl.map_shared_rank(L, r - 1) : 0;
    uint32_t* Lnext = (r < CTAS - 1) ? (uint32_t*)cl.map_shared_rank(L, r + 1) : 0;
    int* chp = (t < CTAS) ? (int*)cl.map_shared_rank(sCh, t) : 0;

    // Per-slot precompute; masks hoisted to registers.
    bool act[SLOTS];
    int  lbs[SLOTS];
    uint32_t pmx[SLOTS], pmy[SLOTS], pmz[SLOTS], tailm[SLOTS];
    #pragma unroll
    for (int s = 0; s < SLOTS; s++) {
        int k = wid * SLOTS + s;
        act[s] = (k < OWNW);
        int kk = act[s] ? k : 0;
        int gw = ow0 + kk;
        int p  = gw * 32 + lane;
        ushort4 pm = __ldg(&g_pm[p]);
        pmx[s] = pm.x; pmy[s] = pm.y; pmz[s] = pm.z;
        int rem = p % ROWBITS;
        int b   = rem % 5;
        lbs[s]  = (LBASE + kk) * 32 + lane - b - 5;
        tailm[s] = ((gw % 9) == 8) ? 0xFu : 0xFFFFFFFFu;
    }

    cl.sync();   // init visible cluster-wide

    int R = 0;       // dirty-map slot receiving halo diffs / first inner read
    int fslot = 0;   // rotating cross-CTA flag slot
    for (int os = 0; os < NBOX; os++) {
        // --- halo refresh with diff tracking into dm[R] ---
        if (t < 9) {
            if (Lprev) {
                int li = t + 1;
                uint32_t nv = Lprev[OWNW + li];          // prev's last row
                if (nv != L[li]) {
                    L[li] = nv;
                    atomicOr(&dm[R][li >> 5], 1u << (li & 31));
                }
            }
        } else if (t >= 32 && t < 41) {
            if (Lnext) {
                int k  = t - 32;
                int li = LBASE + OWNW + k;
                uint32_t nv = Lnext[LBASE + k];          // next's first row
                if (nv != L[li]) {
                    L[li] = nv;
                    atomicOr(&dm[R][li >> 5], 1u << (li & 31));
                }
            }
        }
        if (t == NMS_T - 1) sCh[fslot == 2 ? 0 : fslot + 1] = 0;
        __syncthreads();

        // --- inner: local fixpoint with dirty-window frontier ---
        int ra = R;
        int dirty0 = 0;
        for (int it = 0; it < 256; it++) {
            int wa = (ra == 2) ? 0 : ra + 1;
            int za = (wa == 2) ? 0 : wa + 1;
            if (t < 5) dm[za][t] = 0;

            uint32_t chm = 0;
            #pragma unroll
            for (int s = 0; s < SLOTS; s++) {
                if (!act[s]) continue;
                int li = LBASE + wid * SLOTS + s;
                int bi = li - 10;                        // window [li-10, li+10]
                uint64_t win = (uint64_t)dm[ra][bi >> 5] |
                               ((uint64_t)dm[ra][(bi >> 5) + 1] << 32);
                if (((win >> (bi & 31)) & 0x1FFFFFu) == 0) continue;

                int lb = lbs[s];
                uint32_t gu = gather15(L, lb - ROWBITS);
                uint32_t gm = gather15(L, lb);
                uint32_t gd = gather15(L, lb + ROWBITS);
                uint32_t sup = (gu & pmx[s]) | (gm & pmy[s]) | (gd & pmz[s]);
                uint32_t nw = __ballot_sync(0xFFFFFFFFu, sup == 0u) & tailm[s];
                if (lane == 0 && L[li] != nw) { L[li] = nw; chm |= 1u << s; }
            }

            int ch = 0;
            if (lane == 0 && chm) {
                ch = 1;
                int bb = LBASE + wid * SLOTS;            // dirty bits base
                uint64_t m = (uint64_t)chm << (bb & 31);
                atomicOr(&dm[wa][bb >> 5], (uint32_t)m);
                uint32_t hi = (uint32_t)(m >> 32);
                if (hi) atomicOr(&dm[wa][(bb >> 5) + 1], hi);
            }
            int any = __syncthreads_or(ch);
            if (it == 0) dirty0 = any;
            ra = wa;
            if (!any) break;
        }
        R = ra;   // empty (or pending-marks) slot for next sweep's halo diffs

        // --- cross-CTA convergence exchange ---
        if (t == 0 && dirty0) sCh[fslot] = 1;
        cl.sync();                                       // L + flags visible

        bool mine = (t < CTAS) ? (chp[fslot] != 0) : false;
        uint32_t bal = __ballot_sync(0xFFFFFFFFu, mine);
        if (t == 0) sAny = (int)(bal & 0xFu);
        __syncthreads();
        if (!sAny) break;
        fslot = (fslot == 2) ? 0 : fslot + 1;
    }

    // Writeout: score if kept else 0, own words only.
    #pragma unroll
    for (int s = 0; s < SLOTS; s++) {
        if (!act[s]) continue;
        int k  = wid * SLOTS + s;
        int gw = ow0 + k;
        int p  = gw * 32 + lane;
        int row = p / ROWBITS;
        int rem = p - row * ROWBITS;
        if (rem < 260) {
            int j = row * 260 + rem;
            bool keep = (L[LBASE + k] >> lane) & 1u;
            out[j * 5 + 4] = keep ? __ldg(&x[j * 5 + 4]) : 0.0f;
        }
    }
}

// ---------------------------------------------------------------------------
extern "C" void kernel_launch(void* const* d_in, const int* in_sizes, int n_in,
                              void* d_out, int out_size)
{
    const float* x   = (const float*)d_in[0];
    float*       out = (float*)d_out;

    decode_kernel<<<(3 * NBOX + 255) / 256, 256>>>(x, out);
    nms_kernel<<<CTAS, NMS_T>>>(x, out);
}